// round 12
// baseline (speedup 1.0000x reference)
#include <cuda_runtime.h>
#include <math.h>

#define BB 16
#define TT 4096
#define DD 512

// ---------------- device scratch (no allocations allowed) ----------------
__device__ float g_w0[DD], g_w1[DD], g_w2[DD], g_gw[DD];
__device__ float g_C0, g_C1;                 // sum(beta*w), sum(gamma*w)
__device__ float g_scale[BB], g_sumalpha[BB];
__device__ int4  g_evi[BB * (TT + 1)];       // (s, e, pos, lead-bits)
__device__ float g_evc[BB * (TT + 1)];       // end coefficient
__device__ int   g_nev[BB];

// ---------------- K_pre: transpose conv weights, reduce constants --------
__global__ void cif_pre(const float* __restrict__ cw,
                        const float* __restrict__ gam,
                        const float* __restrict__ bet,
                        const float* __restrict__ pw) {
    int d = threadIdx.x;  // 512 threads
    float w0 = cw[3 * d + 0], w1 = cw[3 * d + 1], w2 = cw[3 * d + 2];
    g_w0[d] = w0; g_w1[d] = w1; g_w2[d] = w2;
    float gw = gam[d] * pw[d];
    float bw = bet[d] * pw[d];
    g_gw[d] = gw;
    __shared__ float sh1[512], sh2[512];
    sh1[d] = gw; sh2[d] = bw;
    __syncthreads();
    for (int off = 256; off; off >>= 1) {
        if (d < off) { sh1[d] += sh1[d + off]; sh2[d] += sh2[d + off]; }
        __syncthreads();
    }
    if (d == 0) { g_C1 = sh1[0]; g_C0 = sh2[0]; }
}

// ---------------- K_alpha: conv + LN + sigmoid gate + zero out rows ------
__global__ void __launch_bounds__(256)
cif_alpha(const float* __restrict__ enc, const int* __restrict__ ilen,
          const float* __restrict__ projb, float* __restrict__ alpha,
          float* __restrict__ out) {
    int b = blockIdx.y;
    int warp = threadIdx.x >> 5, lane = threadIdx.x & 31;
    int len = __ldg(&ilen[b]);
    float pb = __ldg(projb);
    const float* base = enc + (size_t)b * TT * DD;
    float C0 = g_C0, C1 = g_C1;
    int t0 = blockIdx.x * 64 + warp * 8;

    float s1[8], s2[8], sg[8];
#pragma unroll
    for (int i = 0; i < 8; i++) { s1[i] = 0.f; s2[i] = 0.f; sg[i] = 0.f; }

#pragma unroll
    for (int j = 0; j < 4; j++) {
        int d = j * 128 + lane * 4;
        float4 w0 = *(const float4*)(g_w0 + d);
        float4 w1 = *(const float4*)(g_w1 + d);
        float4 w2 = *(const float4*)(g_w2 + d);
        float4 gw = *(const float4*)(g_gw + d);
        const float* p = base + (size_t)t0 * DD + d;
        float4 prv = make_float4(0.f, 0.f, 0.f, 0.f);
        if (t0 > 0) prv = *(const float4*)(p - DD);
        float4 cur = *(const float4*)(p);
#pragma unroll
        for (int i = 0; i < 8; i++) {
            float4 nxt = make_float4(0.f, 0.f, 0.f, 0.f);
            if (t0 + i < TT - 1) nxt = *(const float4*)(p + (size_t)(i + 1) * DD);
            float yx = w0.x * prv.x + w1.x * cur.x + w2.x * nxt.x;
            float yy = w0.y * prv.y + w1.y * cur.y + w2.y * nxt.y;
            float yz = w0.z * prv.z + w1.z * cur.z + w2.z * nxt.z;
            float yw = w0.w * prv.w + w1.w * cur.w + w2.w * nxt.w;
            s1[i] += yx + yy + yz + yw;
            s2[i] += yx * yx + yy * yy + yz * yz + yw * yw;
            sg[i] += yx * gw.x + yy * gw.y + yz * gw.z + yw * gw.w;
            prv = cur; cur = nxt;
        }
    }

#pragma unroll
    for (int i = 0; i < 8; i++) {
        float a1 = s1[i], a2 = s2[i], a3 = sg[i];
#pragma unroll
        for (int off = 16; off; off >>= 1) {
            a1 += __shfl_xor_sync(0xffffffffu, a1, off);
            a2 += __shfl_xor_sync(0xffffffffu, a2, off);
            a3 += __shfl_xor_sync(0xffffffffu, a3, off);
        }
        if (lane == 0) {
            int t = t0 + i;
            float mu  = a1 * (1.0f / DD);
            float var = a2 * (1.0f / DD) - mu * mu;
            float rs  = 1.0f / sqrtf(var + 1e-5f);
            float logit = rs * (a3 - mu * C1) + C0 + pb;
            float a = 1.0f / (1.0f + expf(-logit));
            if (t >= len) a = 0.f;
            alpha[(size_t)b * TT + t] = a;
        }
    }

    // zero this block's 64 out rows (replaces the 134MB memset launch)
    float4 z4 = make_float4(0.f, 0.f, 0.f, 0.f);
    float4* ob = (float4*)(out + ((size_t)b * TT + (size_t)blockIdx.x * 64) * DD);
#pragma unroll 4
    for (int i = threadIdx.x; i < 64 * DD / 4; i += 256) ob[i] = z4;
}

// ---------------- K_scan: pure-FADD chain + zero-prefix recovery ---------
// Per 16-step block: plain chain n_i = n_{i-1}+a_i (bit-exact no-fire
// recurrence, 4cy/step), fire mask off-chain. No fire -> acc=n15, no STS.
// Fire at i0 -> reference-exact rem/ovf from n[i0-1], then RE-RUN the same
// straight-line chain with av_k zeroed for k<=i0 and base=ovf. fl(x+0)=x,
// so recovered values are bit-identical to serial-from-ovf. Spurious low
// bits cleared via `live` mask. No switch, no per-step branches.
__global__ void __launch_bounds__(32)
cif_scan(const float* __restrict__ alpha, const int* __restrict__ ilen,
         const int* __restrict__ tlen) {
    __shared__ float sh[TT];
    __shared__ float sh_n[16];
    int b = blockIdx.x;
    int lane = threadIdx.x;

    // stage alpha[b] into smem; fixed-order partial sums (deterministic)
    const float4* al4 = (const float4*)(alpha + (size_t)b * TT);
    float4* sh4 = (float4*)sh;
    float psum = 0.f;
    for (int k = lane; k < TT / 4; k += 32) {
        float4 v = __ldg(al4 + k);
        sh4[k] = v;
        psum += ((v.x + v.y) + (v.z + v.w));
    }
#pragma unroll
    for (int off = 16; off; off >>= 1)
        psum += __shfl_xor_sync(0xffffffffu, psum, off);
    float tgt = (float)__ldg(&tlen[b]);
    float scale = tgt / fmaxf(psum, 1e-8f);
    if (lane == 0) { g_sumalpha[b] = psum; g_scale[b] = scale; }
    __syncwarp();
    // pre-scale in place (matches reference alpha_cif = alpha * scale)
    for (int k = lane; k < TT / 4; k += 32) {
        float4 v = sh4[k];
        v.x *= scale; v.y *= scale; v.z *= scale; v.w *= scale;
        sh4[k] = v;
    }
    __syncwarp();
    if (lane != 0) return;

    int len = __ldg(&ilen[b]);
    int4*  evi = g_evi + b * (TT + 1);
    float* evc = g_evc + b * (TT + 1);

    float acc = 0.f;
    float P = sh[0];            // lead coeff of first segment if no fire yet
    int s = 0, nev = 0;

    for (int t0 = 0; t0 < TT; t0 += 16) {
        float4 v0 = sh4[t0 / 4 + 0];
        float4 v1 = sh4[t0 / 4 + 1];
        float4 v2 = sh4[t0 / 4 + 2];
        float4 v3 = sh4[t0 / 4 + 3];
        float av0 = v0.x, av1 = v0.y, av2  = v0.z, av3  = v0.w;
        float av4 = v1.x, av5 = v1.y, av6  = v1.z, av7  = v1.w;
        float av8 = v2.x, av9 = v2.y, av10 = v2.z, av11 = v2.w;
        float av12 = v3.x, av13 = v3.y, av14 = v3.z, av15 = v3.w;

        float base = acc;
        unsigned live = 0xFFFFu;

        for (;;) {
            // pure FADD chain (speculative only past a fire; exact otherwise)
            float n0  = base + av0;
            float n1  = n0  + av1;
            float n2  = n1  + av2;
            float n3  = n2  + av3;
            float n4  = n3  + av4;
            float n5  = n4  + av5;
            float n6  = n5  + av6;
            float n7  = n6  + av7;
            float n8  = n7  + av8;
            float n9  = n8  + av9;
            float n10 = n9  + av10;
            float n11 = n10 + av11;
            float n12 = n11 + av12;
            float n13 = n12 + av13;
            float n14 = n13 + av14;
            float n15 = n14 + av15;
            unsigned m = 0;
            m |= (n0  >= 1.0f) ? 0x0001u : 0u;  m |= (n1  >= 1.0f) ? 0x0002u : 0u;
            m |= (n2  >= 1.0f) ? 0x0004u : 0u;  m |= (n3  >= 1.0f) ? 0x0008u : 0u;
            m |= (n4  >= 1.0f) ? 0x0010u : 0u;  m |= (n5  >= 1.0f) ? 0x0020u : 0u;
            m |= (n6  >= 1.0f) ? 0x0040u : 0u;  m |= (n7  >= 1.0f) ? 0x0080u : 0u;
            m |= (n8  >= 1.0f) ? 0x0100u : 0u;  m |= (n9  >= 1.0f) ? 0x0200u : 0u;
            m |= (n10 >= 1.0f) ? 0x0400u : 0u;  m |= (n11 >= 1.0f) ? 0x0800u : 0u;
            m |= (n12 >= 1.0f) ? 0x1000u : 0u;  m |= (n13 >= 1.0f) ? 0x2000u : 0u;
            m |= (n14 >= 1.0f) ? 0x4000u : 0u;  m |= (n15 >= 1.0f) ? 0x8000u : 0u;
            m &= live;
            if (m == 0) { acc = n15; break; }

            sh_n[0]  = n0;  sh_n[1]  = n1;  sh_n[2]  = n2;  sh_n[3]  = n3;
            sh_n[4]  = n4;  sh_n[5]  = n5;  sh_n[6]  = n6;  sh_n[7]  = n7;
            sh_n[8]  = n8;  sh_n[9]  = n9;  sh_n[10] = n10; sh_n[11] = n11;
            sh_n[12] = n12; sh_n[13] = n13; sh_n[14] = n14; sh_n[15] = n15;

            int i0 = __ffs(m) - 1;
            float accb = (i0 == 0) ? base : sh_n[i0 - 1];
            float a0  = sh[t0 + i0];
            float rem = fmaxf(1.0f - accb, 0.0f);
            float ovf = fmaxf(a0 - rem, 0.0f);
            evi[nev] = make_int4(s, t0 + i0, nev, __float_as_int(P));
            evc[nev] = rem;
            nev++;
            s = t0 + i0; P = ovf;
            if (i0 == 15) { acc = ovf; break; }

            base = ovf;
            live = 0xFFFFu << (i0 + 1);
            // zero the consumed prefix (constant-index predicated SELs)
            av0  = 0.f;
            av1  = (1  <= i0) ? 0.f : av1;   av2  = (2  <= i0) ? 0.f : av2;
            av3  = (3  <= i0) ? 0.f : av3;   av4  = (4  <= i0) ? 0.f : av4;
            av5  = (5  <= i0) ? 0.f : av5;   av6  = (6  <= i0) ? 0.f : av6;
            av7  = (7  <= i0) ? 0.f : av7;   av8  = (8  <= i0) ? 0.f : av8;
            av9  = (9  <= i0) ? 0.f : av9;   av10 = (10 <= i0) ? 0.f : av10;
            av11 = (11 <= i0) ? 0.f : av11;  av12 = (12 <= i0) ? 0.f : av12;
            av13 = (13 <= i0) ? 0.f : av13;  av14 = (14 <= i0) ? 0.f : av14;
            av15 = (15 <= i0) ? 0.f : av15;
        }
    }

    // tail fire: emb = wsum (no rem term); clamp end to last valid step.
    if (acc > 0.5f && nev < TT) {
        int e = len - 1;
        if (e < s) e = s;
        float endc = (e == s) ? P : sh[e];
        evi[nev] = make_int4(s, e, nev, __float_as_int(P));
        evc[nev] = endc;
        nev++;
    }
    g_nev[b] = nev;
}

// ---------------- K_gather: one block per event, segmented weighted sum --
// 4x-unrolled interior loop for MLP. Block (0,0) also computes qty loss.
__global__ void __launch_bounds__(128)
cif_gather(const float* __restrict__ enc, const float* __restrict__ alpha,
           const int* __restrict__ tlen,
           float* __restrict__ out, float* __restrict__ qty) {
    int b = blockIdx.x;
    if (b == 0 && blockIdx.y == 0 && threadIdx.x < 32) {
        int i = threadIdx.x;
        float v = (i < BB) ? fabsf(g_sumalpha[i] - (float)__ldg(&tlen[i])) : 0.f;
#pragma unroll
        for (int off = 16; off; off >>= 1) v += __shfl_xor_sync(0xffffffffu, v, off);
        if (i == 0) *qty = v * (1.0f / BB);
    }

    int nev = g_nev[b];
    float scale = g_scale[b];
    const float*  al = alpha + (size_t)b * TT;
    const float4* eb = (const float4*)(enc + (size_t)b * TT * DD);
    int tid = threadIdx.x;  // 128 threads x float4 = 512 channels

    for (int n = blockIdx.y; n < nev; n += gridDim.y) {
        int4  r    = g_evi[b * (TT + 1) + n];
        float endc = g_evc[b * (TT + 1) + n];
        int s = r.x, e = r.y, pos = r.z;
        float lead = __int_as_float(r.w);

        float4 hs = eb[(size_t)s * (DD / 4) + tid];
        float4 acc;
        if (s == e) {
            acc.x = endc * hs.x; acc.y = endc * hs.y;
            acc.z = endc * hs.z; acc.w = endc * hs.w;
        } else {
            float4 he = eb[(size_t)e * (DD / 4) + tid];
            acc.x = lead * hs.x + endc * he.x;
            acc.y = lead * hs.y + endc * he.y;
            acc.z = lead * hs.z + endc * he.z;
            acc.w = lead * hs.w + endc * he.w;
            int t = s + 1;
            for (; t + 4 <= e; t += 4) {
                float c0 = __ldg(&al[t + 0]) * scale;
                float c1 = __ldg(&al[t + 1]) * scale;
                float c2 = __ldg(&al[t + 2]) * scale;
                float c3 = __ldg(&al[t + 3]) * scale;
                float4 h0 = eb[(size_t)(t + 0) * (DD / 4) + tid];
                float4 h1 = eb[(size_t)(t + 1) * (DD / 4) + tid];
                float4 h2 = eb[(size_t)(t + 2) * (DD / 4) + tid];
                float4 h3 = eb[(size_t)(t + 3) * (DD / 4) + tid];
                acc.x += c0 * h0.x + c1 * h1.x + c2 * h2.x + c3 * h3.x;
                acc.y += c0 * h0.y + c1 * h1.y + c2 * h2.y + c3 * h3.y;
                acc.z += c0 * h0.z + c1 * h1.z + c2 * h2.z + c3 * h3.z;
                acc.w += c0 * h0.w + c1 * h1.w + c2 * h2.w + c3 * h3.w;
            }
            for (; t < e; t++) {
                float  c = __ldg(&al[t]) * scale;
                float4 h = eb[(size_t)t * (DD / 4) + tid];
                acc.x += c * h.x; acc.y += c * h.y;
                acc.z += c * h.z; acc.w += c * h.w;
            }
        }
        float4* ob = (float4*)(out + ((size_t)b * TT + pos) * DD);
        ob[tid] = acc;
    }
}

// ---------------- launcher ------------------------------------------------
extern "C" void kernel_launch(void* const* d_in, const int* in_sizes, int n_in,
                              void* d_out, int out_size) {
    const float* enc   = (const float*)d_in[0];
    const int*   ilen  = (const int*)d_in[1];
    const int*   tlen  = (const int*)d_in[2];
    const float* convw = (const float*)d_in[3];
    const float* gam   = (const float*)d_in[4];
    const float* bet   = (const float*)d_in[5];
    const float* projw = (const float*)d_in[6];
    const float* projb = (const float*)d_in[7];

    float* out   = (float*)d_out;
    float* alpha = out + (size_t)BB * TT * DD;
    float* qty   = alpha + (size_t)BB * TT;

    cif_pre<<<1, 512>>>(convw, gam, bet, projw);
    cif_alpha<<<dim3(TT / 64, BB), 256>>>(enc, ilen, projb, alpha, out);
    cif_scan<<<BB, 32>>>(alpha, ilen, tlen);
    cif_gather<<<dim3(BB, 256), 128>>>(enc, alpha, tlen, out, qty);
}

// round 13
// speedup vs baseline: 1.2326x; 1.2326x over previous
#include <cuda_runtime.h>
#include <math.h>

#define BB 16
#define TT 4096
#define DD 512

// ---------------- device scratch (no allocations allowed) ----------------
__device__ float g_w0[DD], g_w1[DD], g_w2[DD], g_gw[DD];
__device__ float g_C0, g_C1;                 // sum(beta*w), sum(gamma*w)
__device__ float g_scale[BB], g_sumalpha[BB];
__device__ int4  g_evi[BB * (TT + 1)];       // (s, e, pos, lead-bits)
__device__ float g_evc[BB * (TT + 1)];       // end coefficient
__device__ int   g_nev[BB];

// ---------------- K_pre: transpose conv weights, reduce constants --------
__global__ void cif_pre(const float* __restrict__ cw,
                        const float* __restrict__ gam,
                        const float* __restrict__ bet,
                        const float* __restrict__ pw) {
    int d = threadIdx.x;  // 512 threads
    float w0 = cw[3 * d + 0], w1 = cw[3 * d + 1], w2 = cw[3 * d + 2];
    g_w0[d] = w0; g_w1[d] = w1; g_w2[d] = w2;
    float gw = gam[d] * pw[d];
    float bw = bet[d] * pw[d];
    g_gw[d] = gw;
    __shared__ float sh1[512], sh2[512];
    sh1[d] = gw; sh2[d] = bw;
    __syncthreads();
    for (int off = 256; off; off >>= 1) {
        if (d < off) { sh1[d] += sh1[d + off]; sh2[d] += sh2[d + off]; }
        __syncthreads();
    }
    if (d == 0) { g_C1 = sh1[0]; g_C0 = sh2[0]; }
}

// ---------------- K_alpha: depthwise conv + LN + sigmoid gate ------------
// Blocks entirely beyond input_length just write zeros (exact: reference
// masks alpha to 0 there) and skip all encoder loads.
__global__ void __launch_bounds__(256)
cif_alpha(const float* __restrict__ enc, const int* __restrict__ ilen,
          const float* __restrict__ projb, float* __restrict__ alpha) {
    int b = blockIdx.y;
    int len = __ldg(&ilen[b]);
    int tblk = blockIdx.x * 64;

    if (tblk >= len) {                         // fully-masked block
        if (threadIdx.x < 64)
            alpha[(size_t)b * TT + tblk + threadIdx.x] = 0.f;
        return;
    }

    int warp = threadIdx.x >> 5, lane = threadIdx.x & 31;
    float pb = __ldg(projb);
    const float* base = enc + (size_t)b * TT * DD;
    float C0 = g_C0, C1 = g_C1;
    int t0 = tblk + warp * 8;

    float s1[8], s2[8], sg[8];
#pragma unroll
    for (int i = 0; i < 8; i++) { s1[i] = 0.f; s2[i] = 0.f; sg[i] = 0.f; }

#pragma unroll
    for (int j = 0; j < 4; j++) {
        int d = j * 128 + lane * 4;
        float4 w0 = *(const float4*)(g_w0 + d);
        float4 w1 = *(const float4*)(g_w1 + d);
        float4 w2 = *(const float4*)(g_w2 + d);
        float4 gw = *(const float4*)(g_gw + d);
        const float* p = base + (size_t)t0 * DD + d;
        float4 prv = make_float4(0.f, 0.f, 0.f, 0.f);
        if (t0 > 0) prv = *(const float4*)(p - DD);
        float4 cur = *(const float4*)(p);
#pragma unroll
        for (int i = 0; i < 8; i++) {
            float4 nxt = make_float4(0.f, 0.f, 0.f, 0.f);
            if (t0 + i < TT - 1) nxt = *(const float4*)(p + (size_t)(i + 1) * DD);
            float yx = w0.x * prv.x + w1.x * cur.x + w2.x * nxt.x;
            float yy = w0.y * prv.y + w1.y * cur.y + w2.y * nxt.y;
            float yz = w0.z * prv.z + w1.z * cur.z + w2.z * nxt.z;
            float yw = w0.w * prv.w + w1.w * cur.w + w2.w * nxt.w;
            s1[i] += yx + yy + yz + yw;
            s2[i] += yx * yx + yy * yy + yz * yz + yw * yw;
            sg[i] += yx * gw.x + yy * gw.y + yz * gw.z + yw * gw.w;
            prv = cur; cur = nxt;
        }
    }

#pragma unroll
    for (int i = 0; i < 8; i++) {
        float a1 = s1[i], a2 = s2[i], a3 = sg[i];
#pragma unroll
        for (int off = 16; off; off >>= 1) {
            a1 += __shfl_xor_sync(0xffffffffu, a1, off);
            a2 += __shfl_xor_sync(0xffffffffu, a2, off);
            a3 += __shfl_xor_sync(0xffffffffu, a3, off);
        }
        if (lane == 0) {
            int t = t0 + i;
            float mu  = a1 * (1.0f / DD);
            float var = a2 * (1.0f / DD) - mu * mu;
            float rs  = 1.0f / sqrtf(var + 1e-5f);
            float logit = rs * (a3 - mu * C1) + C0 + pb;
            float a = 1.0f / (1.0f + expf(-logit));
            if (t >= len) a = 0.f;
            alpha[(size_t)b * TT + t] = a;
        }
    }
}

// ---------------- K_scan: exact inline FSEL recurrence, mask epilogue ----
// (measured-best R8 core) + exact padding cut: for t >= len, a == 0 so
// na == acc (fl exact) and no fire unless acc >= 1, in which case the
// reference fires exactly ONCE on the first pad step (rem = 0, ovf = 0,
// acc -> 0, no further fires). Loop truncated at len (rounded to 16);
// that single phantom fire emitted explicitly. Bit-exact in all regimes.
__global__ void __launch_bounds__(32)
cif_scan(const float* __restrict__ alpha, const int* __restrict__ ilen,
         const int* __restrict__ tlen) {
    __shared__ float sh[TT];
    __shared__ float sh_rem[16];
    int b = blockIdx.x;
    int lane = threadIdx.x;

    // stage alpha[b] into smem; fixed-order partial sums (deterministic)
    const float4* al4 = (const float4*)(alpha + (size_t)b * TT);
    float4* sh4 = (float4*)sh;
    float psum = 0.f;
    for (int k = lane; k < TT / 4; k += 32) {
        float4 v = __ldg(al4 + k);
        sh4[k] = v;
        psum += ((v.x + v.y) + (v.z + v.w));
    }
#pragma unroll
    for (int off = 16; off; off >>= 1)
        psum += __shfl_xor_sync(0xffffffffu, psum, off);
    float tgt = (float)__ldg(&tlen[b]);
    float scale = tgt / fmaxf(psum, 1e-8f);
    if (lane == 0) { g_sumalpha[b] = psum; g_scale[b] = scale; }
    __syncwarp();
    // pre-scale in place (matches reference alpha_cif = alpha * scale)
    for (int k = lane; k < TT / 4; k += 32) {
        float4 v = sh4[k];
        v.x *= scale; v.y *= scale; v.z *= scale; v.w *= scale;
        sh4[k] = v;
    }
    __syncwarp();
    if (lane != 0) return;

    int len = __ldg(&ilen[b]);
    int4*  evi = g_evi + b * (TT + 1);
    float* evc = g_evc + b * (TT + 1);

    float acc = 0.f;
    float P = sh[0];            // lead coeff of first segment if no fire yet
    int s = 0, nev = 0;

    int lenp = (len + 15) & ~15;
    if (lenp > TT) lenp = TT;

    for (int t0 = 0; t0 < lenp; t0 += 16) {
        float av[16];
#pragma unroll
        for (int k = 0; k < 4; k++) {
            float4 v = sh4[t0 / 4 + k];
            av[4 * k + 0] = v.x; av[4 * k + 1] = v.y;
            av[4 * k + 2] = v.z; av[4 * k + 3] = v.w;
        }
        unsigned m = 0;
#pragma unroll
        for (int i = 0; i < 16; i++) {
            float a   = av[i];
            float rem = fmaxf(1.0f - acc, 0.0f);
            float na  = acc + a;
            float ovf = fmaxf(a - rem, 0.0f);
            bool  p   = (na >= 1.0f);
            acc = p ? ovf : na;              // exact update, FSEL
            m |= p ? (1u << i) : 0u;         // off-chain
            sh_rem[i] = rem;                 // off-chain STS snapshot
        }
        if (m) {
            do {
                int i = __ffs(m) - 1;
                m &= m - 1;
                float rem_i = sh_rem[i];
                float a_i   = sh[t0 + i];
                float ovf_i = fmaxf(a_i - rem_i, 0.0f);  // same ops -> exact
                evi[nev] = make_int4(s, t0 + i, nev, __float_as_int(P));
                evc[nev] = rem_i;
                nev++;
                s = t0 + i; P = ovf_i;
            } while (m);
        }
    }

    // phantom fire on first pad step if acc >= 1 (reference fires once with
    // a = 0: rem = fmax(1-acc,0) = 0, ovf = fmax(0-rem,0) = 0, acc -> 0).
    if (len < TT && acc >= 1.0f && nev < TT) {
        float rem = fmaxf(1.0f - acc, 0.0f);
        float ovf = fmaxf(0.0f - rem, 0.0f);
        evi[nev] = make_int4(s, len, nev, __float_as_int(P));
        evc[nev] = rem;
        nev++;
        s = len; P = ovf; acc = ovf;
    }

    // tail fire: emb = wsum (no rem term); clamp end to last valid step.
    if (acc > 0.5f && nev < TT) {
        int e = len - 1;
        if (e < s) e = s;
        float endc = (e == s) ? P : sh[e];
        evi[nev] = make_int4(s, e, nev, __float_as_int(P));
        evc[nev] = endc;
        nev++;
    }
    g_nev[b] = nev;
}

// ---------------- K_gather: one block per event, segmented weighted sum --
// 4x-unrolled interior loop for MLP. Block (0,0) also computes qty loss.
__global__ void __launch_bounds__(128)
cif_gather(const float* __restrict__ enc, const float* __restrict__ alpha,
           const int* __restrict__ tlen,
           float* __restrict__ out, float* __restrict__ qty) {
    int b = blockIdx.x;
    if (b == 0 && blockIdx.y == 0 && threadIdx.x < 32) {
        int i = threadIdx.x;
        float v = (i < BB) ? fabsf(g_sumalpha[i] - (float)__ldg(&tlen[i])) : 0.f;
#pragma unroll
        for (int off = 16; off; off >>= 1) v += __shfl_xor_sync(0xffffffffu, v, off);
        if (i == 0) *qty = v * (1.0f / BB);
    }

    int nev = g_nev[b];
    float scale = g_scale[b];
    const float*  al = alpha + (size_t)b * TT;
    const float4* eb = (const float4*)(enc + (size_t)b * TT * DD);
    int tid = threadIdx.x;  // 128 threads x float4 = 512 channels

    for (int n = blockIdx.y; n < nev; n += gridDim.y) {
        int4  r    = g_evi[b * (TT + 1) + n];
        float endc = g_evc[b * (TT + 1) + n];
        int s = r.x, e = r.y, pos = r.z;
        float lead = __int_as_float(r.w);

        float4 hs = eb[(size_t)s * (DD / 4) + tid];
        float4 acc;
        if (s == e) {
            acc.x = endc * hs.x; acc.y = endc * hs.y;
            acc.z = endc * hs.z; acc.w = endc * hs.w;
        } else {
            float4 he = eb[(size_t)e * (DD / 4) + tid];
            acc.x = lead * hs.x + endc * he.x;
            acc.y = lead * hs.y + endc * he.y;
            acc.z = lead * hs.z + endc * he.z;
            acc.w = lead * hs.w + endc * he.w;
            int t = s + 1;
            for (; t + 4 <= e; t += 4) {
                float c0 = __ldg(&al[t + 0]) * scale;
                float c1 = __ldg(&al[t + 1]) * scale;
                float c2 = __ldg(&al[t + 2]) * scale;
                float c3 = __ldg(&al[t + 3]) * scale;
                float4 h0 = eb[(size_t)(t + 0) * (DD / 4) + tid];
                float4 h1 = eb[(size_t)(t + 1) * (DD / 4) + tid];
                float4 h2 = eb[(size_t)(t + 2) * (DD / 4) + tid];
                float4 h3 = eb[(size_t)(t + 3) * (DD / 4) + tid];
                acc.x += c0 * h0.x + c1 * h1.x + c2 * h2.x + c3 * h3.x;
                acc.y += c0 * h0.y + c1 * h1.y + c2 * h2.y + c3 * h3.y;
                acc.z += c0 * h0.z + c1 * h1.z + c2 * h2.z + c3 * h3.z;
                acc.w += c0 * h0.w + c1 * h1.w + c2 * h2.w + c3 * h3.w;
            }
            for (; t < e; t++) {
                float  c = __ldg(&al[t]) * scale;
                float4 h = eb[(size_t)t * (DD / 4) + tid];
                acc.x += c * h.x; acc.y += c * h.y;
                acc.z += c * h.z; acc.w += c * h.w;
            }
        }
        float4* ob = (float4*)(out + ((size_t)b * TT + pos) * DD);
        ob[tid] = acc;
    }
}

// ---------------- launcher ------------------------------------------------
extern "C" void kernel_launch(void* const* d_in, const int* in_sizes, int n_in,
                              void* d_out, int out_size) {
    const float* enc   = (const float*)d_in[0];
    const int*   ilen  = (const int*)d_in[1];
    const int*   tlen  = (const int*)d_in[2];
    const float* convw = (const float*)d_in[3];
    const float* gam   = (const float*)d_in[4];
    const float* bet   = (const float*)d_in[5];
    const float* projw = (const float*)d_in[6];
    const float* projb = (const float*)d_in[7];

    float* out   = (float*)d_out;
    float* alpha = out + (size_t)BB * TT * DD;
    float* qty   = alpha + (size_t)BB * TT;

    cudaMemsetAsync(out, 0, (size_t)BB * TT * DD * sizeof(float), 0);
    cif_pre<<<1, 512>>>(convw, gam, bet, projw);
    cif_alpha<<<dim3(TT / 64, BB), 256>>>(enc, ilen, projb, alpha);
    cif_scan<<<BB, 32>>>(alpha, ilen, tlen);
    cif_gather<<<dim3(BB, 256), 128>>>(enc, alpha, tlen, out, qty);
}

// round 14
// speedup vs baseline: 1.3333x; 1.0816x over previous
#include <cuda_runtime.h>
#include <math.h>

#define BB 16
#define TT 4096
#define DD 512
#define NZ 112   // zero-worker blocks appended to the scan grid

// ---------------- device scratch (no allocations allowed) ----------------
__device__ float g_w0[DD], g_w1[DD], g_w2[DD], g_gw[DD];
__device__ float g_C0, g_C1;                 // sum(beta*w), sum(gamma*w)
__device__ float g_scale[BB], g_sumalpha[BB];
__device__ int4  g_evi[BB * (TT + 1)];       // (s, e, pos, lead-bits)
__device__ float g_evc[BB * (TT + 1)];       // end coefficient
__device__ int   g_nev[BB];

// ---------------- K_pre: transpose conv weights, reduce constants --------
__global__ void cif_pre(const float* __restrict__ cw,
                        const float* __restrict__ gam,
                        const float* __restrict__ bet,
                        const float* __restrict__ pw) {
    int d = threadIdx.x;  // 512 threads
    float w0 = cw[3 * d + 0], w1 = cw[3 * d + 1], w2 = cw[3 * d + 2];
    g_w0[d] = w0; g_w1[d] = w1; g_w2[d] = w2;
    float gw = gam[d] * pw[d];
    float bw = bet[d] * pw[d];
    g_gw[d] = gw;
    __shared__ float sh1[512], sh2[512];
    sh1[d] = gw; sh2[d] = bw;
    __syncthreads();
    for (int off = 256; off; off >>= 1) {
        if (d < off) { sh1[d] += sh1[d + off]; sh2[d] += sh2[d + off]; }
        __syncthreads();
    }
    if (d == 0) { g_C1 = sh1[0]; g_C0 = sh2[0]; }
}

// ---------------- K_alpha: depthwise conv + LN + sigmoid gate ------------
// Blocks entirely beyond input_length just write zeros (exact: reference
// masks alpha to 0 there) and skip all encoder loads.
__global__ void __launch_bounds__(256)
cif_alpha(const float* __restrict__ enc, const int* __restrict__ ilen,
          const float* __restrict__ projb, float* __restrict__ alpha) {
    int b = blockIdx.y;
    int len = __ldg(&ilen[b]);
    int tblk = blockIdx.x * 64;

    if (tblk >= len) {                         // fully-masked block
        if (threadIdx.x < 64)
            alpha[(size_t)b * TT + tblk + threadIdx.x] = 0.f;
        return;
    }

    int warp = threadIdx.x >> 5, lane = threadIdx.x & 31;
    float pb = __ldg(projb);
    const float* base = enc + (size_t)b * TT * DD;
    float C0 = g_C0, C1 = g_C1;
    int t0 = tblk + warp * 8;

    float s1[8], s2[8], sg[8];
#pragma unroll
    for (int i = 0; i < 8; i++) { s1[i] = 0.f; s2[i] = 0.f; sg[i] = 0.f; }

#pragma unroll
    for (int j = 0; j < 4; j++) {
        int d = j * 128 + lane * 4;
        float4 w0 = *(const float4*)(g_w0 + d);
        float4 w1 = *(const float4*)(g_w1 + d);
        float4 w2 = *(const float4*)(g_w2 + d);
        float4 gw = *(const float4*)(g_gw + d);
        const float* p = base + (size_t)t0 * DD + d;
        float4 prv = make_float4(0.f, 0.f, 0.f, 0.f);
        if (t0 > 0) prv = *(const float4*)(p - DD);
        float4 cur = *(const float4*)(p);
#pragma unroll
        for (int i = 0; i < 8; i++) {
            float4 nxt = make_float4(0.f, 0.f, 0.f, 0.f);
            if (t0 + i < TT - 1) nxt = *(const float4*)(p + (size_t)(i + 1) * DD);
            float yx = w0.x * prv.x + w1.x * cur.x + w2.x * nxt.x;
            float yy = w0.y * prv.y + w1.y * cur.y + w2.y * nxt.y;
            float yz = w0.z * prv.z + w1.z * cur.z + w2.z * nxt.z;
            float yw = w0.w * prv.w + w1.w * cur.w + w2.w * nxt.w;
            s1[i] += yx + yy + yz + yw;
            s2[i] += yx * yx + yy * yy + yz * yz + yw * yw;
            sg[i] += yx * gw.x + yy * gw.y + yz * gw.z + yw * gw.w;
            prv = cur; cur = nxt;
        }
    }

#pragma unroll
    for (int i = 0; i < 8; i++) {
        float a1 = s1[i], a2 = s2[i], a3 = sg[i];
#pragma unroll
        for (int off = 16; off; off >>= 1) {
            a1 += __shfl_xor_sync(0xffffffffu, a1, off);
            a2 += __shfl_xor_sync(0xffffffffu, a2, off);
            a3 += __shfl_xor_sync(0xffffffffu, a3, off);
        }
        if (lane == 0) {
            int t = t0 + i;
            float mu  = a1 * (1.0f / DD);
            float var = a2 * (1.0f / DD) - mu * mu;
            float rs  = 1.0f / sqrtf(var + 1e-5f);
            float logit = rs * (a3 - mu * C1) + C0 + pb;
            float a = 1.0f / (1.0f + expf(-logit));
            if (t >= len) a = 0.f;
            alpha[(size_t)b * TT + t] = a;
        }
    }
}

// ---------------- K_scan: exact FSEL recurrence + fused output zeroing ---
// Blocks [0,BB): warp 0 runs the measured-best R12 scan (bit-identical:
// same staging order, same psum order, same recurrence). Warps 1-7 exit.
// Blocks [BB, BB+NZ): stream-zero 1/NZ of `out` each — runs on the 132
// otherwise-idle SMs, entirely hidden behind the scan's ~60us.
__global__ void __launch_bounds__(256)
cif_scan(const float* __restrict__ alpha, const int* __restrict__ ilen,
         const int* __restrict__ tlen, float* __restrict__ out) {
    int bid = blockIdx.x;

    if (bid >= BB) {  // ---------------- zero-worker block ----------------
        const size_t total = (size_t)BB * TT * DD / 4;      // float4 count
        const size_t per   = (total + NZ - 1) / NZ;
        size_t lo = (size_t)(bid - BB) * per + threadIdx.x;
        size_t hi = (size_t)(bid - BB + 1) * per;
        if (hi > total) hi = total;
        float4 z4 = make_float4(0.f, 0.f, 0.f, 0.f);
        float4* o4 = (float4*)out;
#pragma unroll 4
        for (size_t i = lo; i < hi; i += 256) o4[i] = z4;
        return;
    }

    if (threadIdx.x >= 32) return;   // scan path: warp 0 only (bit-identical)

    __shared__ float sh[TT];
    __shared__ float sh_rem[16];
    int b = bid;
    int lane = threadIdx.x;

    // stage alpha[b] into smem; fixed-order partial sums (deterministic)
    const float4* al4 = (const float4*)(alpha + (size_t)b * TT);
    float4* sh4 = (float4*)sh;
    float psum = 0.f;
    for (int k = lane; k < TT / 4; k += 32) {
        float4 v = __ldg(al4 + k);
        sh4[k] = v;
        psum += ((v.x + v.y) + (v.z + v.w));
    }
#pragma unroll
    for (int off = 16; off; off >>= 1)
        psum += __shfl_xor_sync(0xffffffffu, psum, off);
    float tgt = (float)__ldg(&tlen[b]);
    float scale = tgt / fmaxf(psum, 1e-8f);
    if (lane == 0) { g_sumalpha[b] = psum; g_scale[b] = scale; }
    __syncwarp();
    // pre-scale in place (matches reference alpha_cif = alpha * scale)
    for (int k = lane; k < TT / 4; k += 32) {
        float4 v = sh4[k];
        v.x *= scale; v.y *= scale; v.z *= scale; v.w *= scale;
        sh4[k] = v;
    }
    __syncwarp();
    if (lane != 0) return;

    int len = __ldg(&ilen[b]);
    int4*  evi = g_evi + b * (TT + 1);
    float* evc = g_evc + b * (TT + 1);

    float acc = 0.f;
    float P = sh[0];            // lead coeff of first segment if no fire yet
    int s = 0, nev = 0;

    int lenp = (len + 15) & ~15;
    if (lenp > TT) lenp = TT;

    for (int t0 = 0; t0 < lenp; t0 += 16) {
        float av[16];
#pragma unroll
        for (int k = 0; k < 4; k++) {
            float4 v = sh4[t0 / 4 + k];
            av[4 * k + 0] = v.x; av[4 * k + 1] = v.y;
            av[4 * k + 2] = v.z; av[4 * k + 3] = v.w;
        }
        unsigned m = 0;
#pragma unroll
        for (int i = 0; i < 16; i++) {
            float a   = av[i];
            float rem = fmaxf(1.0f - acc, 0.0f);
            float na  = acc + a;
            float ovf = fmaxf(a - rem, 0.0f);
            bool  p   = (na >= 1.0f);
            acc = p ? ovf : na;              // exact update, FSEL
            m |= p ? (1u << i) : 0u;         // off-chain
            sh_rem[i] = rem;                 // off-chain STS snapshot
        }
        if (m) {
            do {
                int i = __ffs(m) - 1;
                m &= m - 1;
                float rem_i = sh_rem[i];
                float a_i   = sh[t0 + i];
                float ovf_i = fmaxf(a_i - rem_i, 0.0f);  // same ops -> exact
                evi[nev] = make_int4(s, t0 + i, nev, __float_as_int(P));
                evc[nev] = rem_i;
                nev++;
                s = t0 + i; P = ovf_i;
            } while (m);
        }
    }

    // phantom fire on first pad step if acc >= 1 (reference fires once with
    // a = 0: rem = fmax(1-acc,0) = 0, ovf = fmax(0-rem,0) = 0, acc -> 0).
    if (len < TT && acc >= 1.0f && nev < TT) {
        float rem = fmaxf(1.0f - acc, 0.0f);
        float ovf = fmaxf(0.0f - rem, 0.0f);
        evi[nev] = make_int4(s, len, nev, __float_as_int(P));
        evc[nev] = rem;
        nev++;
        s = len; P = ovf; acc = ovf;
    }

    // tail fire: emb = wsum (no rem term); clamp end to last valid step.
    if (acc > 0.5f && nev < TT) {
        int e = len - 1;
        if (e < s) e = s;
        float endc = (e == s) ? P : sh[e];
        evi[nev] = make_int4(s, e, nev, __float_as_int(P));
        evc[nev] = endc;
        nev++;
    }
    g_nev[b] = nev;
}

// ---------------- K_gather: one block per event, segmented weighted sum --
// 4x-unrolled interior loop for MLP. Block (0,0) also computes qty loss.
__global__ void __launch_bounds__(128)
cif_gather(const float* __restrict__ enc, const float* __restrict__ alpha,
           const int* __restrict__ tlen,
           float* __restrict__ out, float* __restrict__ qty) {
    int b = blockIdx.x;
    if (b == 0 && blockIdx.y == 0 && threadIdx.x < 32) {
        int i = threadIdx.x;
        float v = (i < BB) ? fabsf(g_sumalpha[i] - (float)__ldg(&tlen[i])) : 0.f;
#pragma unroll
        for (int off = 16; off; off >>= 1) v += __shfl_xor_sync(0xffffffffu, v, off);
        if (i == 0) *qty = v * (1.0f / BB);
    }

    int nev = g_nev[b];
    float scale = g_scale[b];
    const float*  al = alpha + (size_t)b * TT;
    const float4* eb = (const float4*)(enc + (size_t)b * TT * DD);
    int tid = threadIdx.x;  // 128 threads x float4 = 512 channels

    for (int n = blockIdx.y; n < nev; n += gridDim.y) {
        int4  r    = g_evi[b * (TT + 1) + n];
        float endc = g_evc[b * (TT + 1) + n];
        int s = r.x, e = r.y, pos = r.z;
        float lead = __int_as_float(r.w);

        float4 hs = eb[(size_t)s * (DD / 4) + tid];
        float4 acc;
        if (s == e) {
            acc.x = endc * hs.x; acc.y = endc * hs.y;
            acc.z = endc * hs.z; acc.w = endc * hs.w;
        } else {
            float4 he = eb[(size_t)e * (DD / 4) + tid];
            acc.x = lead * hs.x + endc * he.x;
            acc.y = lead * hs.y + endc * he.y;
            acc.z = lead * hs.z + endc * he.z;
            acc.w = lead * hs.w + endc * he.w;
            int t = s + 1;
            for (; t + 4 <= e; t += 4) {
                float c0 = __ldg(&al[t + 0]) * scale;
                float c1 = __ldg(&al[t + 1]) * scale;
                float c2 = __ldg(&al[t + 2]) * scale;
                float c3 = __ldg(&al[t + 3]) * scale;
                float4 h0 = eb[(size_t)(t + 0) * (DD / 4) + tid];
                float4 h1 = eb[(size_t)(t + 1) * (DD / 4) + tid];
                float4 h2 = eb[(size_t)(t + 2) * (DD / 4) + tid];
                float4 h3 = eb[(size_t)(t + 3) * (DD / 4) + tid];
                acc.x += c0 * h0.x + c1 * h1.x + c2 * h2.x + c3 * h3.x;
                acc.y += c0 * h0.y + c1 * h1.y + c2 * h2.y + c3 * h3.y;
                acc.z += c0 * h0.z + c1 * h1.z + c2 * h2.z + c3 * h3.z;
                acc.w += c0 * h0.w + c1 * h1.w + c2 * h2.w + c3 * h3.w;
            }
            for (; t < e; t++) {
                float  c = __ldg(&al[t]) * scale;
                float4 h = eb[(size_t)t * (DD / 4) + tid];
                acc.x += c * h.x; acc.y += c * h.y;
                acc.z += c * h.z; acc.w += c * h.w;
            }
        }
        float4* ob = (float4*)(out + ((size_t)b * TT + pos) * DD);
        ob[tid] = acc;
    }
}

// ---------------- launcher ------------------------------------------------
extern "C" void kernel_launch(void* const* d_in, const int* in_sizes, int n_in,
                              void* d_out, int out_size) {
    const float* enc   = (const float*)d_in[0];
    const int*   ilen  = (const int*)d_in[1];
    const int*   tlen  = (const int*)d_in[2];
    const float* convw = (const float*)d_in[3];
    const float* gam   = (const float*)d_in[4];
    const float* bet   = (const float*)d_in[5];
    const float* projw = (const float*)d_in[6];
    const float* projb = (const float*)d_in[7];

    float* out   = (float*)d_out;
    float* alpha = out + (size_t)BB * TT * DD;
    float* qty   = alpha + (size_t)BB * TT;

    cif_pre<<<1, 512>>>(convw, gam, bet, projw);
    cif_alpha<<<dim3(TT / 64, BB), 256>>>(enc, ilen, projb, alpha);
    cif_scan<<<BB + NZ, 256>>>(alpha, ilen, tlen, out);
    cif_gather<<<dim3(BB, 256), 128>>>(enc, alpha, tlen, out, qty);
}